// round 4
// baseline (speedup 1.0000x reference)
#include <cuda_runtime.h>
#include <cuda_bf16.h>
#include <cstdint>
#include <math.h>

#define NB 128
#define NT 8
#define ND 2048
#define NR 4
#define NV 512
#define NN 8192   // V*R*R

// ---------------- scratch (no allocation allowed) ----------------
__device__ __nv_bfloat16 g_xbar[NB * ND];   // mean over T, bf16
__device__ float g_alpha[NB * NR];
__device__ float g_beta[NB * NR];
__device__ float g_core[NB * NN];           // |xbar @ w_vocab|
__device__ float g_marg[NB * 16];           // sum_v core  (atomic-accumulated)
__device__ float g_loss[NB];
__device__ int g_done_cnt;                  // zero-init; self-resetting

// =================================================================
// Kernel A: xbar = mean_t(input_embs), alpha/beta = |xbar @ w_{a,b}|
// also zeroes g_marg for this replay (runs before gemm in stream)
// =================================================================
__global__ __launch_bounds__(256) void prep_kernel(
    const float* __restrict__ x, const float* __restrict__ wa,
    const float* __restrict__ wb) {
  const int b = blockIdx.x;
  const int tid = threadIdx.x;
  const int lane = tid & 31;
  const int warp = tid >> 5;
  const float* xb = x + (size_t)b * NT * ND;

  if (tid < 16) g_marg[b * 16 + tid] = 0.f;

  float p[8] = {0.f, 0.f, 0.f, 0.f, 0.f, 0.f, 0.f, 0.f};
  for (int d = tid; d < ND; d += 256) {
    float s = 0.f;
#pragma unroll
    for (int t = 0; t < NT; t++) s += xb[t * ND + d];
    s *= 0.125f;
    g_xbar[b * ND + d] = __float2bfloat16(s);
    float4 a4 = *reinterpret_cast<const float4*>(wa + d * 4);
    float4 b4 = *reinterpret_cast<const float4*>(wb + d * 4);
    p[0] += s * a4.x; p[1] += s * a4.y; p[2] += s * a4.z; p[3] += s * a4.w;
    p[4] += s * b4.x; p[5] += s * b4.y; p[6] += s * b4.z; p[7] += s * b4.w;
  }

  __shared__ float sred[8][8];
#pragma unroll
  for (int q = 0; q < 8; q++) {
    float v = p[q];
#pragma unroll
    for (int o = 16; o; o >>= 1) v += __shfl_xor_sync(0xFFFFFFFFu, v, o);
    if (lane == 0) sred[warp][q] = v;
  }
  __syncthreads();
  if (tid < 8) {
    float s = 0.f;
#pragma unroll
    for (int w = 0; w < 8; w++) s += sred[w][tid];
    s = fabsf(s);
    if (tid < 4) g_alpha[b * 4 + tid] = s;
    else         g_beta[b * 4 + (tid - 4)] = s;
  }
}

// =================================================================
// Kernel B: core = |xbar[128,2048] @ wv[2048,8192]|  (bf16 HMMA)
// 128 blocks (BN=64), 256 threads (8 warps: 4 in M x 2 in N)
// BM=128, BN=64, BK=64, double-buffered smem + DEPTH-2 reg prefetch
// epilogue: |.| store + atomicAdd partial marg sums
// =================================================================
__device__ __forceinline__ void ldsm_x4(unsigned& r0, unsigned& r1,
                                        unsigned& r2, unsigned& r3,
                                        unsigned addr) {
  asm volatile("ldmatrix.sync.aligned.m8n8.x4.shared.b16 {%0,%1,%2,%3}, [%4];"
               : "=r"(r0), "=r"(r1), "=r"(r2), "=r"(r3) : "r"(addr));
}
__device__ __forceinline__ void ldsm_x4_t(unsigned& r0, unsigned& r1,
                                          unsigned& r2, unsigned& r3,
                                          unsigned addr) {
  asm volatile("ldmatrix.sync.aligned.m8n8.x4.trans.shared.b16 {%0,%1,%2,%3}, [%4];"
               : "=r"(r0), "=r"(r1), "=r"(r2), "=r"(r3) : "r"(addr));
}
__device__ __forceinline__ void mma16816(float& c0, float& c1, float& c2, float& c3,
                                         unsigned a0, unsigned a1, unsigned a2,
                                         unsigned a3, unsigned b0, unsigned b1) {
  asm volatile(
      "mma.sync.aligned.m16n8k16.row.col.f32.bf16.bf16.f32 "
      "{%0,%1,%2,%3}, {%4,%5,%6,%7}, {%8,%9}, {%0,%1,%2,%3};"
      : "+f"(c0), "+f"(c1), "+f"(c2), "+f"(c3)
      : "r"(a0), "r"(a1), "r"(a2), "r"(a3), "r"(b0), "r"(b1));
}

__global__ __launch_bounds__(256, 1) void gemm_kernel(const float* __restrict__ wv) {
  __shared__ __align__(16) __nv_bfloat16 Ash[2][128 * 64];  // 32 KB
  __shared__ __align__(16) __nv_bfloat16 Bsh[2][64 * 64];   // 16 KB

  const int tid = threadIdx.x;
  const int lane = tid & 31;
  const int warp = tid >> 5;
  const int wm = warp & 3;   // M group
  const int wn = warp >> 2;  // N group
  const int n0 = blockIdx.x * 64;

  float c[2][4][4];
#pragma unroll
  for (int mi = 0; mi < 2; mi++)
#pragma unroll
    for (int ni = 0; ni < 4; ni++)
#pragma unroll
      for (int q = 0; q < 4; q++) c[mi][ni][q] = 0.f;

  const unsigned aBase = (unsigned)__cvta_generic_to_shared(&Ash[0][0]);
  const unsigned bBase = (unsigned)__cvta_generic_to_shared(&Bsh[0][0]);
  const int lm = lane & 15;
  const int lh = lane >> 4;  // 0/1

  // depth-2 register staging: data(c) lives in buffer c&1
  uint4 ar[2][4];
  float4 br[2][4];

  auto ldg = [&](int it, int rb) {
    const int k0 = it * 64;
#pragma unroll
    for (int i = 0; i < 4; i++) {
      int idx = tid + 256 * i;
      int row = idx >> 3, ch = idx & 7;       // A: 128 rows x 8 chunks of 16B
      ar[rb][i] = *reinterpret_cast<const uint4*>(&g_xbar[row * ND + k0 + ch * 8]);
    }
#pragma unroll
    for (int i = 0; i < 4; i++) {
      int idx = tid + 256 * i;
      int row = idx >> 4, f4 = idx & 15;      // B: 64 rows x 16 float4
      br[rb][i] = *reinterpret_cast<const float4*>(wv + (size_t)(k0 + row) * NN + n0 + f4 * 4);
    }
  };
  auto sts = [&](int buf, int rb) {
#pragma unroll
    for (int i = 0; i < 4; i++) {
      int idx = tid + 256 * i;
      int row = idx >> 3, ch = idx & 7;
      int s = row * 64 + ((ch ^ (row & 7)) << 3);      // XOR swizzle, bf16 units
      *reinterpret_cast<uint4*>(&Ash[buf][s]) = ar[rb][i];
    }
#pragma unroll
    for (int i = 0; i < 4; i++) {
      int idx = tid + 256 * i;
      int row = idx >> 4, f4 = idx & 15;
      __nv_bfloat162 lo = __floats2bfloat162_rn(br[rb][i].x, br[rb][i].y);
      __nv_bfloat162 hi = __floats2bfloat162_rn(br[rb][i].z, br[rb][i].w);
      int s = row * 64 + (((f4 >> 1) ^ (row & 7)) << 3) + (f4 & 1) * 4;
      unsigned* p = reinterpret_cast<unsigned*>(&Bsh[buf][s]);
      p[0] = *reinterpret_cast<unsigned*>(&lo);
      p[1] = *reinterpret_cast<unsigned*>(&hi);
    }
  };
  auto compute = [&](int buf) {
    const unsigned aB = aBase + buf * (128 * 64 * 2);
    const unsigned bB = bBase + buf * (64 * 64 * 2);
#pragma unroll
    for (int ks = 0; ks < 4; ks++) {
      unsigned a[2][4], bf[4][2];
#pragma unroll
      for (int mi = 0; mi < 2; mi++) {
        int mrow = wm * 32 + mi * 16 + lm;
        int kc = ks * 2 + lh;
        int s = mrow * 64 + ((kc ^ (mrow & 7)) << 3);
        ldsm_x4(a[mi][0], a[mi][1], a[mi][2], a[mi][3], aB + s * 2);
      }
#pragma unroll
      for (int ni2 = 0; ni2 < 2; ni2++) {
        int kr = ks * 16 + lm;
        int nch = wn * 4 + ni2 * 2 + lh;
        int s = kr * 64 + ((nch ^ (kr & 7)) << 3);
        unsigned r0, r1, r2, r3;
        ldsm_x4_t(r0, r1, r2, r3, bB + s * 2);
        bf[ni2 * 2 + 0][0] = r0; bf[ni2 * 2 + 0][1] = r1;
        bf[ni2 * 2 + 1][0] = r2; bf[ni2 * 2 + 1][1] = r3;
      }
#pragma unroll
      for (int mi = 0; mi < 2; mi++)
#pragma unroll
        for (int ni = 0; ni < 4; ni++)
          mma16816(c[mi][ni][0], c[mi][ni][1], c[mi][ni][2], c[mi][ni][3],
                   a[mi][0], a[mi][1], a[mi][2], a[mi][3],
                   bf[ni][0], bf[ni][1]);
    }
  };

  // prologue: two loads in flight, stage 0 committed
  ldg(0, 0);
  ldg(1, 1);
  sts(0, 0);
  __syncthreads();
#pragma unroll 1
  for (int it = 0; it < 32; it++) {
    if (it < 30) ldg(it + 2, it & 1);     // depth-2 prefetch
    compute(it & 1);
    if (it < 31) {
      sts((it + 1) & 1, (it + 1) & 1);
      __syncthreads();
    }
  }

  // epilogue: |.|, store fp32 core, accumulate marg partials
  const int iblk = n0 >> 11;              // i index (R dim), constant per CTA
#pragma unroll
  for (int mi = 0; mi < 2; mi++) {
    const int m = wm * 32 + mi * 16 + (lane >> 2);
    const int j0 = (2 * (lane & 3)) & 3;  // j of even col, j0+1 of odd col
    float pj0_a = 0.f, pj1_a = 0.f, pj0_b = 0.f, pj1_b = 0.f;
#pragma unroll
    for (int ni = 0; ni < 4; ni++) {
      int n = n0 + wn * 32 + ni * 8 + (lane & 3) * 2;
      float v0 = fabsf(c[mi][ni][0]), v1 = fabsf(c[mi][ni][1]);
      float v2 = fabsf(c[mi][ni][2]), v3 = fabsf(c[mi][ni][3]);
      *reinterpret_cast<float2*>(&g_core[(size_t)m * NN + n]) = make_float2(v0, v1);
      *reinterpret_cast<float2*>(&g_core[(size_t)(m + 8) * NN + n]) = make_float2(v2, v3);
      pj0_a += v0; pj1_a += v1; pj0_b += v2; pj1_b += v3;
    }
    atomicAdd(&g_marg[m * 16 + iblk * 4 + j0], pj0_a);
    atomicAdd(&g_marg[m * 16 + iblk * 4 + j0 + 1], pj1_a);
    atomicAdd(&g_marg[(m + 8) * 16 + iblk * 4 + j0], pj0_b);
    atomicAdd(&g_marg[(m + 8) * 16 + iblk * 4 + j0 + 1], pj1_b);
  }
}

// =================================================================
// Kernel C: per-batch label gather, 4x4 chains, loss_b,
// fused last-block mean reduction -> out[0]
// =================================================================
__global__ __launch_bounds__(128) void finalize_kernel(
    const int* __restrict__ labels, float* __restrict__ out) {
  const int b = blockIdx.x;
  const int tid = threadIdx.x;
  const float* cb = g_core + (size_t)b * NN;

  __shared__ float sel[NT][16];
  __shared__ int slab[NT];

  if (tid < NT) slab[tid] = labels[b * NT + tid];
  __syncthreads();
  if (tid < NT * 16) {
    const int t = tid >> 4, q = tid & 15;
    sel[t][q] = cb[(q >> 2) * (NV * NR) + slab[t] * NR + (q & 3)];
  }
  __syncthreads();

  if (tid == 0) {
    float res[16], tmp[16];
#pragma unroll
    for (int q = 0; q < 16; q++) res[q] = sel[0][q];
    for (int t = 1; t < NT; t++) {
#pragma unroll
      for (int ii = 0; ii < 4; ii++)
#pragma unroll
        for (int jj = 0; jj < 4; jj++) {
          float acc = 0.f;
#pragma unroll
          for (int kk = 0; kk < 4; kk++) acc += res[ii * 4 + kk] * sel[t][kk * 4 + jj];
          tmp[ii * 4 + jj] = acc;
        }
#pragma unroll
      for (int q = 0; q < 16; q++) res[q] = tmp[q];
    }
    const float* al = g_alpha + b * 4;
    const float* be = g_beta + b * 4;
    float u = 0.f;
#pragma unroll
    for (int ii = 0; ii < 4; ii++)
#pragma unroll
      for (int jj = 0; jj < 4; jj++) u += al[ii] * res[ii * 4 + jj] * be[jj];

    float marg[16], zc[16];
#pragma unroll
    for (int q = 0; q < 16; q++) { marg[q] = g_marg[b * 16 + q]; zc[q] = marg[q]; }
    for (int t = 0; t < NT; t++) {   // zc = marg^(T+1)
#pragma unroll
      for (int ii = 0; ii < 4; ii++)
#pragma unroll
        for (int jj = 0; jj < 4; jj++) {
          float acc = 0.f;
#pragma unroll
          for (int kk = 0; kk < 4; kk++) acc += zc[ii * 4 + kk] * marg[kk * 4 + jj];
          tmp[ii * 4 + jj] = acc;
        }
#pragma unroll
      for (int q = 0; q < 16; q++) zc[q] = tmp[q];
    }
    float z = 0.f;
#pragma unroll
    for (int ii = 0; ii < 4; ii++)
#pragma unroll
      for (int jj = 0; jj < 4; jj++) z += al[ii] * zc[ii * 4 + jj] * be[jj];

    g_loss[b] = logf(z) - logf(u);   // = -log(u/z)
  }

  // ---- fused mean reduction: last block to finish does it ----
  __shared__ int is_last;
  if (tid == 0) {
    __threadfence();
    int prev = atomicAdd(&g_done_cnt, 1);
    is_last = (prev == NB - 1);
  }
  __syncthreads();
  if (is_last) {
    __threadfence();
    float v = g_loss[tid];
#pragma unroll
    for (int o = 16; o; o >>= 1) v += __shfl_xor_sync(0xFFFFFFFFu, v, o);
    __shared__ float sw[4];
    if ((tid & 31) == 0) sw[tid >> 5] = v;
    __syncthreads();
    if (tid == 0) {
      out[0] = (sw[0] + sw[1] + sw[2] + sw[3]) * (1.0f / 128.0f);
      atomicExch(&g_done_cnt, 0);   // reset for next graph replay
    }
  }
}

// =================================================================
extern "C" void kernel_launch(void* const* d_in, const int* in_sizes, int n_in,
                              void* d_out, int out_size) {
  const float* x      = (const float*)d_in[0];   // [128, 8, 2048]
  const int*   labels = (const int*)  d_in[1];   // [128, 8]
  const float* wa     = (const float*)d_in[2];   // [2048, 4]
  const float* wb     = (const float*)d_in[3];   // [2048, 4]
  const float* wv     = (const float*)d_in[4];   // [2048, 8192]
  float* out = (float*)d_out;

  prep_kernel<<<NB, 256>>>(x, wa, wb);
  gemm_kernel<<<NN / 64, 256>>>(wv);
  finalize_kernel<<<NB, 128>>>(labels, out);
}

// round 6
// speedup vs baseline: 1.6630x; 1.6630x over previous
#include <cuda_runtime.h>
#include <cuda_bf16.h>
#include <cstdint>
#include <math.h>

#define NB 128
#define NT 8
#define ND 2048
#define NR 4
#define NV 512
#define NN 8192   // V*R*R

// ---------------- scratch (no allocation allowed) ----------------
__device__ __nv_bfloat16 g_xbar[NB * ND];   // mean over T, bf16
__device__ float g_alpha[NB * NR];
__device__ float g_beta[NB * NR];
__device__ float g_core[NB * NN];           // |xbar @ w_vocab|
__device__ float g_marg[NB * 16];           // sum_v core  (atomic-accumulated)
__device__ float g_loss[NB];
__device__ int g_done_cnt;                  // zero-init; self-resetting

// =================================================================
// Kernel A: xbar = mean_t(input_embs), alpha/beta = |xbar @ w_{a,b}|
// 512 threads / batch, float4 everywhere, MLP~16.
// Also zeroes g_marg for this replay (stream-ordered before gemm).
// =================================================================
__global__ __launch_bounds__(512) void prep_kernel(
    const float* __restrict__ x, const float* __restrict__ wa,
    const float* __restrict__ wb) {
  const int b = blockIdx.x;
  const int tid = threadIdx.x;
  const int lane = tid & 31;
  const int warp = tid >> 5;
  const int d4 = tid * 4;                      // 512*4 = 2048
  const float* xb = x + (size_t)b * NT * ND + d4;

  if (tid < 16) g_marg[b * 16 + tid] = 0.f;

  // ---- mean over T (8 independent LDG.128) ----
  float4 v[NT];
#pragma unroll
  for (int t = 0; t < NT; t++)
    v[t] = *reinterpret_cast<const float4*>(xb + t * ND);
  float4 s4;
  s4.x = (((v[0].x + v[1].x) + (v[2].x + v[3].x)) +
          ((v[4].x + v[5].x) + (v[6].x + v[7].x))) * 0.125f;
  s4.y = (((v[0].y + v[1].y) + (v[2].y + v[3].y)) +
          ((v[4].y + v[5].y) + (v[6].y + v[7].y))) * 0.125f;
  s4.z = (((v[0].z + v[1].z) + (v[2].z + v[3].z)) +
          ((v[4].z + v[5].z) + (v[6].z + v[7].z))) * 0.125f;
  s4.w = (((v[0].w + v[1].w) + (v[2].w + v[3].w)) +
          ((v[4].w + v[5].w) + (v[6].w + v[7].w))) * 0.125f;

  __nv_bfloat162 lo = __floats2bfloat162_rn(s4.x, s4.y);
  __nv_bfloat162 hi = __floats2bfloat162_rn(s4.z, s4.w);
  uint2 packed;
  packed.x = *reinterpret_cast<unsigned*>(&lo);
  packed.y = *reinterpret_cast<unsigned*>(&hi);
  *reinterpret_cast<uint2*>(&g_xbar[b * ND + d4]) = packed;

  // ---- alpha/beta partials over this thread's 4 d's ----
  float p[8] = {0.f, 0.f, 0.f, 0.f, 0.f, 0.f, 0.f, 0.f};
#pragma unroll
  for (int q = 0; q < 4; q++) {
    const float sd = (&s4.x)[q];
    float4 a4 = *reinterpret_cast<const float4*>(wa + (d4 + q) * 4);
    float4 b4 = *reinterpret_cast<const float4*>(wb + (d4 + q) * 4);
    p[0] += sd * a4.x; p[1] += sd * a4.y; p[2] += sd * a4.z; p[3] += sd * a4.w;
    p[4] += sd * b4.x; p[5] += sd * b4.y; p[6] += sd * b4.z; p[7] += sd * b4.w;
  }

  __shared__ float sred[16][8];
#pragma unroll
  for (int q = 0; q < 8; q++) {
    float vv = p[q];
#pragma unroll
    for (int o = 16; o; o >>= 1) vv += __shfl_xor_sync(0xFFFFFFFFu, vv, o);
    if (lane == 0) sred[warp][q] = vv;
  }
  __syncthreads();
  if (tid < 8) {
    float s = 0.f;
#pragma unroll
    for (int w = 0; w < 16; w++) s += sred[w][tid];
    s = fabsf(s);
    if (tid < 4) g_alpha[b * 4 + tid] = s;
    else         g_beta[b * 4 + (tid - 4)] = s;
  }
}

// =================================================================
// Kernel B: core = |xbar[128,2048] @ wv[2048,8192]|  (bf16 HMMA)
// 128 blocks (BN=64), 256 threads (8 warps: 4 in M x 2 in N)
// BM=128, BN=64, BK=64, double-buffered smem + depth-1 reg prefetch
// ks-fragments double-buffered (ldsm overlaps mma)
// epilogue: |.| store + atomicAdd partial marg sums
// =================================================================
__device__ __forceinline__ void ldsm_x4(unsigned& r0, unsigned& r1,
                                        unsigned& r2, unsigned& r3,
                                        unsigned addr) {
  asm volatile("ldmatrix.sync.aligned.m8n8.x4.shared.b16 {%0,%1,%2,%3}, [%4];"
               : "=r"(r0), "=r"(r1), "=r"(r2), "=r"(r3) : "r"(addr));
}
__device__ __forceinline__ void ldsm_x4_t(unsigned& r0, unsigned& r1,
                                          unsigned& r2, unsigned& r3,
                                          unsigned addr) {
  asm volatile("ldmatrix.sync.aligned.m8n8.x4.trans.shared.b16 {%0,%1,%2,%3}, [%4];"
               : "=r"(r0), "=r"(r1), "=r"(r2), "=r"(r3) : "r"(addr));
}
__device__ __forceinline__ void mma16816(float& c0, float& c1, float& c2, float& c3,
                                         unsigned a0, unsigned a1, unsigned a2,
                                         unsigned a3, unsigned b0, unsigned b1) {
  asm volatile(
      "mma.sync.aligned.m16n8k16.row.col.f32.bf16.bf16.f32 "
      "{%0,%1,%2,%3}, {%4,%5,%6,%7}, {%8,%9}, {%0,%1,%2,%3};"
      : "+f"(c0), "+f"(c1), "+f"(c2), "+f"(c3)
      : "r"(a0), "r"(a1), "r"(a2), "r"(a3), "r"(b0), "r"(b1));
}

__global__ __launch_bounds__(256, 1) void gemm_kernel(const float* __restrict__ wv) {
  __shared__ __align__(16) __nv_bfloat16 Ash[2][128 * 64];  // 32 KB
  __shared__ __align__(16) __nv_bfloat16 Bsh[2][64 * 64];   // 16 KB

  const int tid = threadIdx.x;
  const int lane = tid & 31;
  const int warp = tid >> 5;
  const int wm = warp & 3;   // M group
  const int wn = warp >> 2;  // N group
  const int n0 = blockIdx.x * 64;

  float c[2][4][4];
#pragma unroll
  for (int mi = 0; mi < 2; mi++)
#pragma unroll
    for (int ni = 0; ni < 4; ni++)
#pragma unroll
      for (int q = 0; q < 4; q++) c[mi][ni][q] = 0.f;

  const unsigned aBase = (unsigned)__cvta_generic_to_shared(&Ash[0][0]);
  const unsigned bBase = (unsigned)__cvta_generic_to_shared(&Bsh[0][0]);
  const int lm = lane & 15;
  const int lh = lane >> 4;  // 0/1

  uint4 ar[4];
  float4 br[4];

  auto ldg = [&](int it) {
    const int k0 = it * 64;
#pragma unroll
    for (int i = 0; i < 4; i++) {
      int idx = tid + 256 * i;
      int row = idx >> 3, ch = idx & 7;       // A: 128 rows x 8 chunks of 16B
      ar[i] = *reinterpret_cast<const uint4*>(&g_xbar[row * ND + k0 + ch * 8]);
    }
#pragma unroll
    for (int i = 0; i < 4; i++) {
      int idx = tid + 256 * i;
      int row = idx >> 4, f4 = idx & 15;      // B: 64 rows x 16 float4
      br[i] = *reinterpret_cast<const float4*>(wv + (size_t)(k0 + row) * NN + n0 + f4 * 4);
    }
  };
  auto sts = [&](int buf) {
#pragma unroll
    for (int i = 0; i < 4; i++) {
      int idx = tid + 256 * i;
      int row = idx >> 3, ch = idx & 7;
      int s = row * 64 + ((ch ^ (row & 7)) << 3);      // XOR swizzle, bf16 units
      *reinterpret_cast<uint4*>(&Ash[buf][s]) = ar[i];
    }
#pragma unroll
    for (int i = 0; i < 4; i++) {
      int idx = tid + 256 * i;
      int row = idx >> 4, f4 = idx & 15;
      __nv_bfloat162 lo = __floats2bfloat162_rn(br[i].x, br[i].y);
      __nv_bfloat162 hi = __floats2bfloat162_rn(br[i].z, br[i].w);
      int s = row * 64 + (((f4 >> 1) ^ (row & 7)) << 3) + (f4 & 1) * 4;
      unsigned* p = reinterpret_cast<unsigned*>(&Bsh[buf][s]);
      p[0] = *reinterpret_cast<unsigned*>(&lo);
      p[1] = *reinterpret_cast<unsigned*>(&hi);
    }
  };

  auto load_frags = [&](unsigned aB, unsigned bB, int ks,
                        unsigned a[2][4], unsigned bf[4][2]) {
#pragma unroll
    for (int mi = 0; mi < 2; mi++) {
      int mrow = wm * 32 + mi * 16 + lm;
      int kc = ks * 2 + lh;
      int s = mrow * 64 + ((kc ^ (mrow & 7)) << 3);
      ldsm_x4(a[mi][0], a[mi][1], a[mi][2], a[mi][3], aB + s * 2);
    }
#pragma unroll
    for (int ni2 = 0; ni2 < 2; ni2++) {
      int kr = ks * 16 + lm;
      int nch = wn * 4 + ni2 * 2 + lh;
      int s = kr * 64 + ((nch ^ (kr & 7)) << 3);
      unsigned r0, r1, r2, r3;
      ldsm_x4_t(r0, r1, r2, r3, bB + s * 2);
      bf[ni2 * 2 + 0][0] = r0; bf[ni2 * 2 + 0][1] = r1;
      bf[ni2 * 2 + 1][0] = r2; bf[ni2 * 2 + 1][1] = r3;
    }
  };

  auto compute = [&](int buf) {
    const unsigned aB = aBase + buf * (128 * 64 * 2);
    const unsigned bB = bBase + buf * (64 * 64 * 2);
    unsigned a[2][2][4], bf[2][4][2];     // double-buffered fragments
    load_frags(aB, bB, 0, a[0], bf[0]);
#pragma unroll
    for (int ks = 0; ks < 4; ks++) {
      const int cur = ks & 1;
      if (ks < 3) load_frags(aB, bB, ks + 1, a[cur ^ 1], bf[cur ^ 1]);
#pragma unroll
      for (int mi = 0; mi < 2; mi++)
#pragma unroll
        for (int ni = 0; ni < 4; ni++)
          mma16816(c[mi][ni][0], c[mi][ni][1], c[mi][ni][2], c[mi][ni][3],
                   a[cur][mi][0], a[cur][mi][1], a[cur][mi][2], a[cur][mi][3],
                   bf[cur][ni][0], bf[cur][ni][1]);
    }
  };

  ldg(0);
  sts(0);
  __syncthreads();
#pragma unroll 1
  for (int it = 0; it < 32; it++) {
    const int buf = it & 1;
    if (it < 31) ldg(it + 1);           // depth-1 prefetch (proven)
    compute(buf);
    if (it < 31) {
      sts(buf ^ 1);
      __syncthreads();
    }
  }

  // epilogue: |.|, store fp32 core, accumulate marg partials
  const int iblk = n0 >> 11;            // i index (R dim), constant per CTA
#pragma unroll
  for (int mi = 0; mi < 2; mi++) {
    const int m = wm * 32 + mi * 16 + (lane >> 2);
    const int j0 = (2 * (lane & 3)) & 3;  // j of even col; j0+1 for odd col
    float pj0_a = 0.f, pj1_a = 0.f, pj0_b = 0.f, pj1_b = 0.f;
#pragma unroll
    for (int ni = 0; ni < 4; ni++) {
      int n = n0 + wn * 32 + ni * 8 + (lane & 3) * 2;
      float v0 = fabsf(c[mi][ni][0]), v1 = fabsf(c[mi][ni][1]);
      float v2 = fabsf(c[mi][ni][2]), v3 = fabsf(c[mi][ni][3]);
      *reinterpret_cast<float2*>(&g_core[(size_t)m * NN + n]) = make_float2(v0, v1);
      *reinterpret_cast<float2*>(&g_core[(size_t)(m + 8) * NN + n]) = make_float2(v2, v3);
      pj0_a += v0; pj1_a += v1; pj0_b += v2; pj1_b += v3;
    }
    atomicAdd(&g_marg[m * 16 + iblk * 4 + j0], pj0_a);
    atomicAdd(&g_marg[m * 16 + iblk * 4 + j0 + 1], pj1_a);
    atomicAdd(&g_marg[(m + 8) * 16 + iblk * 4 + j0], pj0_b);
    atomicAdd(&g_marg[(m + 8) * 16 + iblk * 4 + j0 + 1], pj1_b);
  }
}

// =================================================================
// Kernel C: per-batch label gather, 4x4 chains, loss_b,
// fused last-block mean reduction -> out[0]
// =================================================================
__global__ __launch_bounds__(128) void finalize_kernel(
    const int* __restrict__ labels, float* __restrict__ out) {
  const int b = blockIdx.x;
  const int tid = threadIdx.x;
  const float* cb = g_core + (size_t)b * NN;

  __shared__ float sel[NT][16];
  __shared__ int slab[NT];

  if (tid < NT) slab[tid] = labels[b * NT + tid];
  __syncthreads();
  if (tid < NT * 16) {
    const int t = tid >> 4, q = tid & 15;
    sel[t][q] = cb[(q >> 2) * (NV * NR) + slab[t] * NR + (q & 3)];
  }
  __syncthreads();

  if (tid == 0) {
    float res[16], tmp[16];
#pragma unroll
    for (int q = 0; q < 16; q++) res[q] = sel[0][q];
    for (int t = 1; t < NT; t++) {
#pragma unroll
      for (int ii = 0; ii < 4; ii++)
#pragma unroll
        for (int jj = 0; jj < 4; jj++) {
          float acc = 0.f;
#pragma unroll
          for (int kk = 0; kk < 4; kk++) acc += res[ii * 4 + kk] * sel[t][kk * 4 + jj];
          tmp[ii * 4 + jj] = acc;
        }
#pragma unroll
      for (int q = 0; q < 16; q++) res[q] = tmp[q];
    }
    const float* al = g_alpha + b * 4;
    const float* be = g_beta + b * 4;
    float u = 0.f;
#pragma unroll
    for (int ii = 0; ii < 4; ii++)
#pragma unroll
      for (int jj = 0; jj < 4; jj++) u += al[ii] * res[ii * 4 + jj] * be[jj];

    float marg[16], zc[16];
#pragma unroll
    for (int q = 0; q < 16; q++) { marg[q] = g_marg[b * 16 + q]; zc[q] = marg[q]; }
    for (int t = 0; t < NT; t++) {   // zc = marg^(T+1)
#pragma unroll
      for (int ii = 0; ii < 4; ii++)
#pragma unroll
        for (int jj = 0; jj < 4; jj++) {
          float acc = 0.f;
#pragma unroll
          for (int kk = 0; kk < 4; kk++) acc += zc[ii * 4 + kk] * marg[kk * 4 + jj];
          tmp[ii * 4 + jj] = acc;
        }
#pragma unroll
      for (int q = 0; q < 16; q++) zc[q] = tmp[q];
    }
    float z = 0.f;
#pragma unroll
    for (int ii = 0; ii < 4; ii++)
#pragma unroll
      for (int jj = 0; jj < 4; jj++) z += al[ii] * zc[ii * 4 + jj] * be[jj];

    g_loss[b] = logf(z) - logf(u);   // = -log(u/z)
  }

  // ---- fused mean reduction: last block to finish does it ----
  __shared__ int is_last;
  if (tid == 0) {
    __threadfence();
    int prev = atomicAdd(&g_done_cnt, 1);
    is_last = (prev == NB - 1);
  }
  __syncthreads();
  if (is_last) {
    __threadfence();
    float v = g_loss[tid];
#pragma unroll
    for (int o = 16; o; o >>= 1) v += __shfl_xor_sync(0xFFFFFFFFu, v, o);
    __shared__ float sw[4];
    if ((tid & 31) == 0) sw[tid >> 5] = v;
    __syncthreads();
    if (tid == 0) {
      out[0] = (sw[0] + sw[1] + sw[2] + sw[3]) * (1.0f / 128.0f);
      atomicExch(&g_done_cnt, 0);   // reset for next graph replay
    }
  }
}

// =================================================================
extern "C" void kernel_launch(void* const* d_in, const int* in_sizes, int n_in,
                              void* d_out, int out_size) {
  const float* x      = (const float*)d_in[0];   // [128, 8, 2048]
  const int*   labels = (const int*)  d_in[1];   // [128, 8]
  const float* wa     = (const float*)d_in[2];   // [2048, 4]
  const float* wb     = (const float*)d_in[3];   // [2048, 4]
  const float* wv     = (const float*)d_in[4];   // [2048, 8192]
  float* out = (float*)d_out;

  prep_kernel<<<NB, 512>>>(x, wa, wb);
  gemm_kernel<<<NN / 64, 256>>>(wv);
  finalize_kernel<<<NB, 128>>>(labels, out);
}